// round 1
// baseline (speedup 1.0000x reference)
#include <cuda_runtime.h>
#include <math.h>
#include <math_constants.h>

// ---------------------------------------------------------------------------
// Problem constants
//   x:   [2, 2048, 1024]   context: [2, 512, 1024]
//   16 heads x 64 dim (MID=1024), NUM_BUCKETS=32, MAX_DIST=128, SCALE=0.125
// ---------------------------------------------------------------------------
#define B        2
#define NQ       2048
#define NCTX     512
#define F        1024
#define MID      1024
#define NHEAD    16
#define HDIM     64
#define ROWS_X   (B * NQ)      // 4096
#define ROWS_C   (B * NCTX)    // 1024

// ---------------------------------------------------------------------------
// Scratch (device globals: no allocation allowed in kernel_launch)
// ---------------------------------------------------------------------------
__device__ float g_xn[ROWS_X * F];        // normed q-side input (reused)
__device__ float g_cn[ROWS_X * F];        // normed kv-side input (reused)
__device__ float g_q [ROWS_X * MID];      // q projection
__device__ float g_kv[ROWS_X * 2 * MID];  // kv projection (worst case self-attn)
__device__ float g_ao[ROWS_X * MID];      // attention output (pre out-proj)
__device__ float g_x1[ROWS_X * F];        // x after self-attention residual

// ---------------------------------------------------------------------------
// LayerNorm: one block (256 thr) per row of 1024
// ---------------------------------------------------------------------------
__global__ __launch_bounds__(256) void ln_kernel(
    const float* __restrict__ x, const float* __restrict__ g,
    const float* __restrict__ bta, float* __restrict__ out)
{
    __shared__ float red[8];
    const int row = blockIdx.x;
    const int tid = threadIdx.x;

    const float4* xr = (const float4*)(x + (size_t)row * F);
    float4 v = xr[tid];

    // sum reduce
    float s = v.x + v.y + v.z + v.w;
    #pragma unroll
    for (int o = 16; o > 0; o >>= 1) s += __shfl_xor_sync(0xffffffffu, s, o);
    if ((tid & 31) == 0) red[tid >> 5] = s;
    __syncthreads();
    float tot = 0.f;
    #pragma unroll
    for (int i = 0; i < 8; i++) tot += red[i];
    const float mean = tot * (1.0f / F);

    // var reduce
    float dx = v.x - mean, dy = v.y - mean, dz = v.z - mean, dw = v.w - mean;
    float sq = dx * dx + dy * dy + dz * dz + dw * dw;
    #pragma unroll
    for (int o = 16; o > 0; o >>= 1) sq += __shfl_xor_sync(0xffffffffu, sq, o);
    __syncthreads();                    // protect red[] reuse
    if ((tid & 31) == 0) red[tid >> 5] = sq;
    __syncthreads();
    float tsq = 0.f;
    #pragma unroll
    for (int i = 0; i < 8; i++) tsq += red[i];
    const float rs = rsqrtf(tsq * (1.0f / F) + 1e-5f);

    const float4 gv = ((const float4*)g)[tid];
    const float4 bv = ((const float4*)bta)[tid];
    float4 o4;
    o4.x = dx * rs * gv.x + bv.x;
    o4.y = dy * rs * gv.y + bv.y;
    o4.z = dz * rs * gv.z + bv.z;
    o4.w = dw * rs * gv.w + bv.w;
    ((float4*)(out + (size_t)row * F))[tid] = o4;
}

// ---------------------------------------------------------------------------
// SGEMM 128x128x8, 256 threads, 8x8 per thread (two 4x4 fragments each dim).
// C[M,N] = A[M,K] @ B[K,N] (+ bias[N]) (+ res[M,N])
// M % 128 == 0, N % 128 == 0, K % 8 == 0 (guaranteed by shapes).
// ---------------------------------------------------------------------------
__global__ __launch_bounds__(256, 2) void gemm128(
    const float* __restrict__ A, const float* __restrict__ Bm,
    float* __restrict__ C, int M, int N, int K,
    const float* __restrict__ bias, const float* __restrict__ res)
{
    __shared__ float As[8][132];
    __shared__ float Bs[8][132];

    const int tid = threadIdx.x;
    const int bm = blockIdx.y * 128;
    const int bn = blockIdx.x * 128;
    const int tx = tid & 15;        // 16 cols of threads
    const int ty = tid >> 4;        // 16 rows of threads

    const int arow = tid >> 1;              // 0..127
    const int acol = (tid & 1) * 4;         // 0 or 4
    const int brow = tid >> 5;              // 0..7
    const int bcol = (tid & 31) * 4;        // 0..124

    const float* Ap = A + (size_t)(bm + arow) * K + acol;
    const float* Bp = Bm + (size_t)brow * N + bn + bcol;

    float acc[8][8];
    #pragma unroll
    for (int i = 0; i < 8; i++)
        #pragma unroll
        for (int j = 0; j < 8; j++) acc[i][j] = 0.f;

    for (int kt = 0; kt < K; kt += 8) {
        float4 a4 = *(const float4*)(Ap + kt);
        As[acol + 0][arow] = a4.x;
        As[acol + 1][arow] = a4.y;
        As[acol + 2][arow] = a4.z;
        As[acol + 3][arow] = a4.w;
        *(float4*)&Bs[brow][bcol] = *(const float4*)(Bp + (size_t)kt * N);
        __syncthreads();

        #pragma unroll
        for (int k = 0; k < 8; k++) {
            float a[8], b[8];
            *(float4*)&a[0] = *(const float4*)&As[k][ty * 4];
            *(float4*)&a[4] = *(const float4*)&As[k][64 + ty * 4];
            *(float4*)&b[0] = *(const float4*)&Bs[k][tx * 4];
            *(float4*)&b[4] = *(const float4*)&Bs[k][64 + tx * 4];
            #pragma unroll
            for (int i = 0; i < 8; i++)
                #pragma unroll
                for (int j = 0; j < 8; j++)
                    acc[i][j] += a[i] * b[j];
        }
        __syncthreads();
    }

    // epilogue: rows {bm+ty*4+i, bm+64+ty*4+i}, cols {bn+tx*4+j, bn+64+tx*4+j}
    #pragma unroll
    for (int i = 0; i < 8; i++) {
        const int row = bm + ((i < 4) ? 0 : 64) + ty * 4 + (i & 3);
        #pragma unroll
        for (int half = 0; half < 2; half++) {
            const int col0 = bn + half * 64 + tx * 4;
            const size_t base = (size_t)row * N + col0;
            float v[4];
            #pragma unroll
            for (int j = 0; j < 4; j++) {
                float t = acc[i][half * 4 + j];
                if (bias) t += bias[col0 + j];
                if (res)  t += res[base + j];
                v[j] = t;
            }
            *(float4*)(C + base) = make_float4(v[0], v[1], v[2], v[3]);
        }
    }
}

// ---------------------------------------------------------------------------
// Attention with T5 relative-position-bucket bias, flash-style.
// Block: 256 threads handles one (batch, head, 64-row q tile).
// Quad of 4 threads per q row; each lane owns 16 of the 64 dims.
// kv layout: [b*m + j][2048], k at col h*64, v at col 1024 + h*64.
// sim = (q.k + bias) * 0.125 ; softmax over m ; out = attn @ v
// ---------------------------------------------------------------------------
__global__ __launch_bounds__(256) void attn_kernel(
    const float* __restrict__ qb, const float* __restrict__ kvb,
    float* __restrict__ ob, const float* __restrict__ rel,
    int n, int m, int mn_off)   // mn_off = m - n
{
    __shared__ float KV[64][68];   // K tile, then reused for V tile
    __shared__ float Ss[64][65];   // scores for this chunk

    const int tid = threadIdx.x;
    const int r   = tid >> 2;      // q row in tile: 0..63
    const int sub = tid & 3;       // dim quarter: 0..3
    const int b   = blockIdx.z;
    const int h   = blockIdx.y;
    const int q0  = blockIdx.x * 64;
    const int qi  = q0 + r;

    // load this thread's 16 q values
    const float* qrow = qb + (size_t)(b * n + qi) * MID + h * HDIM + sub * 16;
    float4 qr[4];
    qr[0] = ((const float4*)qrow)[0];
    qr[1] = ((const float4*)qrow)[1];
    qr[2] = ((const float4*)qrow)[2];
    qr[3] = ((const float4*)qrow)[3];

    float o[16];
    #pragma unroll
    for (int i = 0; i < 16; i++) o[i] = 0.f;
    float m_run = -CUDART_INF_F;
    float l_run = 0.f;

    const int lr = tid >> 2;           // load row 0..63
    const int lc = (tid & 3) * 16;     // load col group

    for (int j0 = 0; j0 < m; j0 += 64) {
        // ---- load K tile ----
        {
            const float* src = kvb + (size_t)(b * m + j0 + lr) * (2 * MID) + h * HDIM + lc;
            float4* dst = (float4*)&KV[lr][lc];
            const float4* s4 = (const float4*)src;
            dst[0] = s4[0]; dst[1] = s4[1]; dst[2] = s4[2]; dst[3] = s4[3];
        }
        __syncthreads();

        // ---- phase A: scores ----
        float cmax = -CUDART_INF_F;
        for (int j = 0; j < 64; j++) {
            const float4* kp = (const float4*)&KV[j][sub * 16];
            float4 k0 = kp[0], k1 = kp[1], k2 = kp[2], k3 = kp[3];
            float part =
                qr[0].x * k0.x + qr[0].y * k0.y + qr[0].z * k0.z + qr[0].w * k0.w +
                qr[1].x * k1.x + qr[1].y * k1.y + qr[1].z * k1.z + qr[1].w * k1.w +
                qr[2].x * k2.x + qr[2].y * k2.y + qr[2].z * k2.z + qr[2].w * k2.w +
                qr[3].x * k3.x + qr[3].y * k3.y + qr[3].z * k3.z + qr[3].w * k3.w;
            part += __shfl_xor_sync(0xffffffffu, part, 1);
            part += __shfl_xor_sync(0xffffffffu, part, 2);

            // T5 relative position bucket (non-causal, 32 buckets, max_dist 128)
            const int relp = (j0 + j) - qi - mn_off;
            const int retv = (relp >= 0) ? 16 : 0;
            const int na = (relp < 0) ? -relp : relp;
            int bucket;
            if (na < 8) {
                bucket = retv + na;
            } else {
                float t = logf((float)na * 0.125f) / 2.7725887f;   // log(16) in f32
                int vl = 8 + (int)(t * 8.0f);
                bucket = retv + min(vl, 15);
            }
            const float s = (part + rel[bucket * NHEAD + h]) * 0.125f;
            cmax = fmaxf(cmax, s);
            if (sub == 0) Ss[r][j] = s;
        }
        __syncthreads();

        // ---- load V tile over K's smem ----
        {
            const float* src = kvb + (size_t)(b * m + j0 + lr) * (2 * MID) + MID + h * HDIM + lc;
            float4* dst = (float4*)&KV[lr][lc];
            const float4* s4 = (const float4*)src;
            dst[0] = s4[0]; dst[1] = s4[1]; dst[2] = s4[2]; dst[3] = s4[3];
        }
        __syncthreads();

        // ---- phase B: online softmax + AV ----
        const float mnew = fmaxf(m_run, cmax);
        const float alpha = expf(m_run - mnew);   // 0 on first chunk
        l_run *= alpha;
        #pragma unroll
        for (int i = 0; i < 16; i++) o[i] *= alpha;

        for (int j = 0; j < 64; j++) {
            const float p = expf(Ss[r][j] - mnew);
            l_run += p;
            const float4* vp = (const float4*)&KV[j][sub * 16];
            float4 v0 = vp[0], v1 = vp[1], v2 = vp[2], v3 = vp[3];
            o[0]  += p * v0.x; o[1]  += p * v0.y; o[2]  += p * v0.z; o[3]  += p * v0.w;
            o[4]  += p * v1.x; o[5]  += p * v1.y; o[6]  += p * v1.z; o[7]  += p * v1.w;
            o[8]  += p * v2.x; o[9]  += p * v2.y; o[10] += p * v2.z; o[11] += p * v2.w;
            o[12] += p * v3.x; o[13] += p * v3.y; o[14] += p * v3.z; o[15] += p * v3.w;
        }
        m_run = mnew;
        __syncthreads();   // before next chunk overwrites KV / Ss
    }

    const float inv = 1.0f / l_run;
    float* orow = ob + (size_t)(b * n + qi) * MID + h * HDIM + sub * 16;
    float4* od = (float4*)orow;
    od[0] = make_float4(o[0] * inv,  o[1] * inv,  o[2] * inv,  o[3] * inv);
    od[1] = make_float4(o[4] * inv,  o[5] * inv,  o[6] * inv,  o[7] * inv);
    od[2] = make_float4(o[8] * inv,  o[9] * inv,  o[10] * inv, o[11] * inv);
    od[3] = make_float4(o[12] * inv, o[13] * inv, o[14] * inv, o[15] * inv);
}

// ---------------------------------------------------------------------------
// Launch
// ---------------------------------------------------------------------------
extern "C" void kernel_launch(void* const* d_in, const int* in_sizes, int n_in,
                              void* d_out, int out_size)
{
    (void)in_sizes; (void)n_in; (void)out_size;

    const float* x       = (const float*)d_in[0];
    const float* ctx     = (const float*)d_in[1];
    const float* sa_ng   = (const float*)d_in[2];
    const float* sa_nb   = (const float*)d_in[3];
    const float* sa_ncg  = (const float*)d_in[4];
    const float* sa_ncb  = (const float*)d_in[5];
    const float* sa_wq   = (const float*)d_in[6];
    const float* sa_wkv  = (const float*)d_in[7];
    const float* sa_wo   = (const float*)d_in[8];
    const float* sa_bo   = (const float*)d_in[9];
    const float* sa_rel  = (const float*)d_in[10];
    const float* ca_ng   = (const float*)d_in[11];
    const float* ca_nb   = (const float*)d_in[12];
    const float* ca_ncg  = (const float*)d_in[13];
    const float* ca_ncb  = (const float*)d_in[14];
    const float* ca_wq   = (const float*)d_in[15];
    const float* ca_wkv  = (const float*)d_in[16];
    const float* ca_wo   = (const float*)d_in[17];
    const float* ca_bo   = (const float*)d_in[18];
    const float* ca_rel  = (const float*)d_in[19];
    float* out = (float*)d_out;

    float *xn, *cn, *q, *kv, *ao, *x1;
    cudaGetSymbolAddress((void**)&xn, g_xn);
    cudaGetSymbolAddress((void**)&cn, g_cn);
    cudaGetSymbolAddress((void**)&q,  g_q);
    cudaGetSymbolAddress((void**)&kv, g_kv);
    cudaGetSymbolAddress((void**)&ao, g_ao);
    cudaGetSymbolAddress((void**)&x1, g_x1);

    // ---------------- self-attention ----------------
    ln_kernel<<<ROWS_X, 256>>>(x, sa_ng,  sa_nb,  xn);
    ln_kernel<<<ROWS_X, 256>>>(x, sa_ncg, sa_ncb, cn);
    gemm128<<<dim3(MID / 128,     ROWS_X / 128), 256>>>(xn, sa_wq,  q,  ROWS_X, MID,     F, nullptr, nullptr);
    gemm128<<<dim3(2 * MID / 128, ROWS_X / 128), 256>>>(cn, sa_wkv, kv, ROWS_X, 2 * MID, F, nullptr, nullptr);
    attn_kernel<<<dim3(NQ / 64, NHEAD, B), 256>>>(q, kv, ao, sa_rel, NQ, NQ, 0);
    gemm128<<<dim3(F / 128, ROWS_X / 128), 256>>>(ao, sa_wo, x1, ROWS_X, F, MID, sa_bo, x);

    // ---------------- cross-attention ----------------
    ln_kernel<<<ROWS_X, 256>>>(x1,  ca_ng,  ca_nb,  xn);
    ln_kernel<<<ROWS_C, 256>>>(ctx, ca_ncg, ca_ncb, cn);
    gemm128<<<dim3(MID / 128,     ROWS_X / 128), 256>>>(xn, ca_wq,  q,  ROWS_X, MID,     F, nullptr, nullptr);
    gemm128<<<dim3(2 * MID / 128, ROWS_C / 128), 256>>>(cn, ca_wkv, kv, ROWS_C, 2 * MID, F, nullptr, nullptr);
    attn_kernel<<<dim3(NQ / 64, NHEAD, B), 256>>>(q, kv, ao, ca_rel, NQ, NCTX, NCTX - NQ);
    gemm128<<<dim3(F / 128, ROWS_X / 128), 256>>>(ao, ca_wo, out, ROWS_X, F, MID, ca_bo, x1);
}

// round 2
// speedup vs baseline: 4.7410x; 4.7410x over previous
#include <cuda_runtime.h>
#include <math.h>
#include <math_constants.h>
#include <stdint.h>

// ---------------------------------------------------------------------------
// Problem constants
// ---------------------------------------------------------------------------
#define B        2
#define NQ       2048
#define NCTX     512
#define F        1024
#define MID      1024
#define NHEAD    16
#define HDIM     64
#define ROWS_X   (B * NQ)      // 4096
#define ROWS_C   (B * NCTX)    // 1024

// ---------------------------------------------------------------------------
// Scratch (device globals)
// ---------------------------------------------------------------------------
__device__ float g_xn[ROWS_X * F];
__device__ float g_cn[ROWS_X * F];
__device__ float g_q [ROWS_X * MID];
__device__ float g_kv[ROWS_X * 2 * MID];
__device__ float g_ao[ROWS_X * MID];
__device__ float g_x1[ROWS_X * F];
__device__ float g_bias[NHEAD * 4096];   // rel-pos bias table, rel in [-2048,2047]

// ---------------------------------------------------------------------------
// tf32 helpers + mma wrapper
// ---------------------------------------------------------------------------
__device__ __forceinline__ uint32_t tf32u(float x) {
    uint32_t r;
    asm("cvt.rna.tf32.f32 %0, %1;" : "=r"(r) : "f"(x));
    return r;
}
__device__ __forceinline__ float tf32f(float x) { return __uint_as_float(tf32u(x)); }

__device__ __forceinline__ void mma_tf32(float c[4], const uint32_t a[4], const uint32_t b[2]) {
    asm volatile(
        "mma.sync.aligned.m16n8k8.row.col.f32.tf32.tf32.f32 "
        "{%0,%1,%2,%3}, {%4,%5,%6,%7}, {%8,%9}, {%0,%1,%2,%3};\n"
        : "+f"(c[0]), "+f"(c[1]), "+f"(c[2]), "+f"(c[3])
        : "r"(a[0]), "r"(a[1]), "r"(a[2]), "r"(a[3]), "r"(b[0]), "r"(b[1]));
}

// ---------------------------------------------------------------------------
// LayerNorm: one block (256 thr) per row of 1024
// ---------------------------------------------------------------------------
__global__ __launch_bounds__(256) void ln_kernel(
    const float* __restrict__ x, const float* __restrict__ g,
    const float* __restrict__ bta, float* __restrict__ out)
{
    __shared__ float red[8];
    const int row = blockIdx.x;
    const int tid = threadIdx.x;

    const float4* xr = (const float4*)(x + (size_t)row * F);
    float4 v = xr[tid];

    float s = v.x + v.y + v.z + v.w;
    #pragma unroll
    for (int o = 16; o > 0; o >>= 1) s += __shfl_xor_sync(0xffffffffu, s, o);
    if ((tid & 31) == 0) red[tid >> 5] = s;
    __syncthreads();
    float tot = 0.f;
    #pragma unroll
    for (int i = 0; i < 8; i++) tot += red[i];
    const float mean = tot * (1.0f / F);

    float dx = v.x - mean, dy = v.y - mean, dz = v.z - mean, dw = v.w - mean;
    float sq = dx * dx + dy * dy + dz * dz + dw * dw;
    #pragma unroll
    for (int o = 16; o > 0; o >>= 1) sq += __shfl_xor_sync(0xffffffffu, sq, o);
    __syncthreads();
    if ((tid & 31) == 0) red[tid >> 5] = sq;
    __syncthreads();
    float tsq = 0.f;
    #pragma unroll
    for (int i = 0; i < 8; i++) tsq += red[i];
    const float rs = rsqrtf(tsq * (1.0f / F) + 1e-5f);

    const float4 gv = ((const float4*)g)[tid];
    const float4 bv = ((const float4*)bta)[tid];
    float4 o4;
    o4.x = dx * rs * gv.x + bv.x;
    o4.y = dy * rs * gv.y + bv.y;
    o4.z = dz * rs * gv.z + bv.z;
    o4.w = dw * rs * gv.w + bv.w;
    ((float4*)(out + (size_t)row * F))[tid] = o4;
}

// ---------------------------------------------------------------------------
// Rel-pos bias table: tbl[h*4096 + rel + 2048] = emb[bucket(rel)*NHEAD + h]
// ---------------------------------------------------------------------------
__global__ __launch_bounds__(256) void bias_table_kernel(
    const float* __restrict__ emb, float* __restrict__ tbl)
{
    const int idx = blockIdx.x * 256 + threadIdx.x;   // 0 .. 65535
    const int h = idx >> 12;
    const int p = idx & 4095;
    const int rel = p - 2048;
    const int retv = (rel >= 0) ? 16 : 0;
    const int na = (rel < 0) ? -rel : rel;
    int bucket;
    if (na < 8) {
        bucket = retv + na;
    } else {
        float t = logf((float)na * 0.125f) / 2.7725887f;   // log(16)
        int vl = 8 + (int)(t * 8.0f);
        bucket = retv + min(vl, 15);
    }
    tbl[h * 4096 + p] = emb[bucket * NHEAD + h];
}

// ---------------------------------------------------------------------------
// tf32 tensor-core GEMM: 128x128 tile, 8 warps (2x4), warp tile 64x32, k=32.
// C[M,N] = A[M,K] @ B[K,N] (+bias[N]) (+res[M,N]).  M%128==N%128==K%32==0.
// ---------------------------------------------------------------------------
__global__ __launch_bounds__(256) void gemm_tc(
    const float* __restrict__ A, const float* __restrict__ Bm,
    float* __restrict__ C, int M, int N, int K,
    const float* __restrict__ bias, const float* __restrict__ res)
{
    __shared__ float As[128][36];   // [row][k], pad->conflict-free frag loads
    __shared__ float Bs[32][136];   // [k][col]

    const int tid  = threadIdx.x;
    const int warp = tid >> 5, lane = tid & 31;
    const int q  = lane >> 2;       // 0..7
    const int cq = lane & 3;        // 0..3
    const int wm = (warp >> 2) * 64;
    const int wn = (warp & 3) * 32;
    const int bm = blockIdx.y * 128, bn = blockIdx.x * 128;

    float acc[4][4][4];
    #pragma unroll
    for (int mt = 0; mt < 4; mt++)
        #pragma unroll
        for (int nt = 0; nt < 4; nt++)
            #pragma unroll
            for (int e = 0; e < 4; e++) acc[mt][nt][e] = 0.f;

    const int ar = tid >> 1;            // A load row 0..127
    const int ac = (tid & 1) * 16;      // A load k base
    const int br = tid >> 3;            // B load k 0..31
    const int bc = (tid & 7) * 16;      // B load col base

    const float* Ap = A + (size_t)(bm + ar) * K + ac;
    const float* Bp = Bm + (size_t)br * N + bn + bc;

    for (int k0 = 0; k0 < K; k0 += 32) {
        #pragma unroll
        for (int i = 0; i < 4; i++) {
            float4 v = *(const float4*)(Ap + k0 + i * 4);
            As[ar][ac + i * 4 + 0] = tf32f(v.x);
            As[ar][ac + i * 4 + 1] = tf32f(v.y);
            As[ar][ac + i * 4 + 2] = tf32f(v.z);
            As[ar][ac + i * 4 + 3] = tf32f(v.w);
        }
        #pragma unroll
        for (int i = 0; i < 4; i++) {
            float4 v = *(const float4*)(Bp + (size_t)k0 * N + i * 4);
            Bs[br][bc + i * 4 + 0] = tf32f(v.x);
            Bs[br][bc + i * 4 + 1] = tf32f(v.y);
            Bs[br][bc + i * 4 + 2] = tf32f(v.z);
            Bs[br][bc + i * 4 + 3] = tf32f(v.w);
        }
        __syncthreads();

        #pragma unroll
        for (int ks = 0; ks < 4; ks++) {
            uint32_t af[4][4], bf[4][2];
            #pragma unroll
            for (int mt = 0; mt < 4; mt++) {
                const int r = wm + mt * 16 + q;
                af[mt][0] = __float_as_uint(As[r    ][ks * 8 + cq]);
                af[mt][1] = __float_as_uint(As[r + 8][ks * 8 + cq]);
                af[mt][2] = __float_as_uint(As[r    ][ks * 8 + cq + 4]);
                af[mt][3] = __float_as_uint(As[r + 8][ks * 8 + cq + 4]);
            }
            #pragma unroll
            for (int nt = 0; nt < 4; nt++) {
                const int col = wn + nt * 8 + q;
                bf[nt][0] = __float_as_uint(Bs[ks * 8 + cq    ][col]);
                bf[nt][1] = __float_as_uint(Bs[ks * 8 + cq + 4][col]);
            }
            #pragma unroll
            for (int mt = 0; mt < 4; mt++)
                #pragma unroll
                for (int nt = 0; nt < 4; nt++)
                    mma_tf32(acc[mt][nt], af[mt], bf[nt]);
        }
        __syncthreads();
    }

    // epilogue
    #pragma unroll
    for (int mt = 0; mt < 4; mt++) {
        const int r0 = bm + wm + mt * 16 + q;
        #pragma unroll
        for (int nt = 0; nt < 4; nt++) {
            const int c0 = bn + wn + nt * 8 + 2 * cq;
            #pragma unroll
            for (int half = 0; half < 2; half++) {
                const int row = r0 + half * 8;
                float v0 = acc[mt][nt][half * 2 + 0];
                float v1 = acc[mt][nt][half * 2 + 1];
                if (bias) { v0 += bias[c0]; v1 += bias[c0 + 1]; }
                const size_t base = (size_t)row * N + c0;
                if (res) { v0 += res[base]; v1 += res[base + 1]; }
                *(float2*)(C + base) = make_float2(v0, v1);
            }
        }
    }
}

// ---------------------------------------------------------------------------
// Flash attention, tf32 MMA. Block = 128 thr (4 warps) = one (b,h,64-q tile).
// Warp w owns q rows [w*16, w*16+16). K/V chunks of 64.
// kv layout: row (b*m+j) stride 2*MID; k at col h*64, v at col MID + h*64.
// ---------------------------------------------------------------------------
__global__ __launch_bounds__(128) void attn_tc(
    const float* __restrict__ qb, const float* __restrict__ kvb,
    float* __restrict__ ob, const float* __restrict__ tbl,
    int n, int m, int mnoff)
{
    __shared__ float KVs[64 * 68];   // K tile [j][d] pad68; reused as V^T [d][j]
    __shared__ float Ps [64 * 68];   // probabilities (tf32 values)
    __shared__ float sb [128];       // rel-pos bias for this chunk

    const int tid  = threadIdx.x;
    const int warp = tid >> 5, lane = tid & 31;
    const int q  = lane >> 2;        // 0..7
    const int cq = lane & 3;         // 0..3
    const int b  = blockIdx.z, h = blockIdx.y;
    const int q0 = blockIdx.x * 64;
    const int wq = warp * 16;
    const int r0l = wq + q;          // local q row of c0,c1
    const int r1l = r0l + 8;         // local q row of c2,c3

    // Q fragments (held in registers for the whole kernel)
    uint32_t qf[8][4];
    {
        const float* qr0 = qb + (size_t)(b * n + q0 + r0l) * MID + h * HDIM;
        const float* qr1 = qr0 + 8 * (size_t)MID;
        #pragma unroll
        for (int ks = 0; ks < 8; ks++) {
            qf[ks][0] = tf32u(qr0[ks * 8 + cq]);
            qf[ks][1] = tf32u(qr1[ks * 8 + cq]);
            qf[ks][2] = tf32u(qr0[ks * 8 + cq + 4]);
            qf[ks][3] = tf32u(qr1[ks * 8 + cq + 4]);
        }
    }

    float o[8][4];
    #pragma unroll
    for (int dt = 0; dt < 8; dt++)
        #pragma unroll
        for (int e = 0; e < 4; e++) o[dt][e] = 0.f;
    float mrun0 = -CUDART_INF_F, mrun1 = -CUDART_INF_F;
    float lrun0 = 0.f, lrun1 = 0.f;

    const int lr = tid >> 1;             // load row (j) 0..63
    const int lh = (tid & 1) * 32;       // dim half
    const float* kvbase = kvb + (size_t)(b * m) * (2 * MID) + h * HDIM;

    for (int j0 = 0; j0 < m; j0 += 64) {
        // bias slice: rel = (j - r) + (j0 - q0 - mnoff), idx = j - r + 63
        if (tid < 127)
            sb[tid] = tbl[h * 4096 + 2048 + (tid - 63) + (j0 - q0 - mnoff)];

        // ---- K tile [j][d] (tf32) ----
        {
            const float* krow = kvbase + (size_t)(j0 + lr) * (2 * MID) + lh;
            float* dst = &KVs[lr * 68 + lh];
            #pragma unroll
            for (int i = 0; i < 8; i++) {
                float4 v = ((const float4*)krow)[i];
                ((float4*)dst)[i] = make_float4(tf32f(v.x), tf32f(v.y), tf32f(v.z), tf32f(v.w));
            }
        }
        __syncthreads();

        // ---- S = Q @ K^T ----
        float s[8][4];
        #pragma unroll
        for (int nt = 0; nt < 8; nt++)
            #pragma unroll
            for (int e = 0; e < 4; e++) s[nt][e] = 0.f;

        #pragma unroll
        for (int ks = 0; ks < 8; ks++) {
            #pragma unroll
            for (int nt = 0; nt < 8; nt++) {
                uint32_t bf[2];
                const int j = nt * 8 + q;
                bf[0] = __float_as_uint(KVs[j * 68 + ks * 8 + cq]);
                bf[1] = __float_as_uint(KVs[j * 68 + ks * 8 + cq + 4]);
                mma_tf32(s[nt], qf[ks], bf);
            }
        }

        // ---- bias + scale + row max ----
        float cmax0 = -CUDART_INF_F, cmax1 = -CUDART_INF_F;
        #pragma unroll
        for (int nt = 0; nt < 8; nt++) {
            #pragma unroll
            for (int e = 0; e < 2; e++) {
                const int j = nt * 8 + 2 * cq + e;
                const float b0 = sb[j - r0l + 63];
                const float b1 = sb[j - r1l + 63];
                s[nt][e]     = (s[nt][e]     + b0) * 0.125f;
                s[nt][2 + e] = (s[nt][2 + e] + b1) * 0.125f;
                cmax0 = fmaxf(cmax0, s[nt][e]);
                cmax1 = fmaxf(cmax1, s[nt][2 + e]);
            }
        }
        cmax0 = fmaxf(cmax0, __shfl_xor_sync(0xffffffffu, cmax0, 1));
        cmax0 = fmaxf(cmax0, __shfl_xor_sync(0xffffffffu, cmax0, 2));
        cmax1 = fmaxf(cmax1, __shfl_xor_sync(0xffffffffu, cmax1, 1));
        cmax1 = fmaxf(cmax1, __shfl_xor_sync(0xffffffffu, cmax1, 2));

        const float mn0 = fmaxf(mrun0, cmax0);
        const float mn1 = fmaxf(mrun1, cmax1);
        const float al0 = __expf(mrun0 - mn0);
        const float al1 = __expf(mrun1 - mn1);

        // ---- exp, partial row sums, write P to smem ----
        float ps0 = 0.f, ps1 = 0.f;
        #pragma unroll
        for (int nt = 0; nt < 8; nt++) {
            #pragma unroll
            for (int e = 0; e < 2; e++) {
                const int j = nt * 8 + 2 * cq + e;
                const float p0 = __expf(s[nt][e] - mn0);
                const float p1 = __expf(s[nt][2 + e] - mn1);
                ps0 += p0;
                ps1 += p1;
                Ps[r0l * 68 + j] = tf32f(p0);
                Ps[r1l * 68 + j] = tf32f(p1);
            }
        }
        ps0 += __shfl_xor_sync(0xffffffffu, ps0, 1);
        ps0 += __shfl_xor_sync(0xffffffffu, ps0, 2);
        ps1 += __shfl_xor_sync(0xffffffffu, ps1, 1);
        ps1 += __shfl_xor_sync(0xffffffffu, ps1, 2);

        lrun0 = lrun0 * al0 + ps0;
        lrun1 = lrun1 * al1 + ps1;
        #pragma unroll
        for (int dt = 0; dt < 8; dt++) {
            o[dt][0] *= al0; o[dt][1] *= al0;
            o[dt][2] *= al1; o[dt][3] *= al1;
        }
        mrun0 = mn0; mrun1 = mn1;
        __syncthreads();   // done reading K, done writing P

        // ---- V tile, transposed: KVs[d][j] ----
        {
            const float* vrow = kvbase + MID + (size_t)(j0 + lr) * (2 * MID) + lh;
            #pragma unroll
            for (int i = 0; i < 8; i++) {
                float4 v = ((const float4*)vrow)[i];
                const int d = lh + i * 4;
                KVs[(d + 0) * 68 + lr] = tf32f(v.x);
                KVs[(d + 1) * 68 + lr] = tf32f(v.y);
                KVs[(d + 2) * 68 + lr] = tf32f(v.z);
                KVs[(d + 3) * 68 + lr] = tf32f(v.w);
            }
        }
        __syncthreads();

        // ---- O += P @ V ----
        #pragma unroll
        for (int ks = 0; ks < 8; ks++) {
            uint32_t af[4];
            af[0] = __float_as_uint(Ps[r0l * 68 + ks * 8 + cq]);
            af[1] = __float_as_uint(Ps[r1l * 68 + ks * 8 + cq]);
            af[2] = __float_as_uint(Ps[r0l * 68 + ks * 8 + cq + 4]);
            af[3] = __float_as_uint(Ps[r1l * 68 + ks * 8 + cq + 4]);
            #pragma unroll
            for (int dt = 0; dt < 8; dt++) {
                uint32_t bf[2];
                const int d = dt * 8 + q;
                bf[0] = __float_as_uint(KVs[d * 68 + ks * 8 + cq]);
                bf[1] = __float_as_uint(KVs[d * 68 + ks * 8 + cq + 4]);
                mma_tf32(o[dt], af, bf);
            }
        }
        __syncthreads();   // before next chunk overwrites KVs / Ps / sb
    }

    // ---- normalize + store ----
    const float inv0 = 1.0f / lrun0;
    const float inv1 = 1.0f / lrun1;
    float* or0 = ob + (size_t)(b * n + q0 + r0l) * MID + h * HDIM;
    float* or1 = ob + (size_t)(b * n + q0 + r1l) * MID + h * HDIM;
    #pragma unroll
    for (int dt = 0; dt < 8; dt++) {
        const int c = dt * 8 + 2 * cq;
        *(float2*)(or0 + c) = make_float2(o[dt][0] * inv0, o[dt][1] * inv0);
        *(float2*)(or1 + c) = make_float2(o[dt][2] * inv1, o[dt][3] * inv1);
    }
}

// ---------------------------------------------------------------------------
// Launch
// ---------------------------------------------------------------------------
extern "C" void kernel_launch(void* const* d_in, const int* in_sizes, int n_in,
                              void* d_out, int out_size)
{
    (void)in_sizes; (void)n_in; (void)out_size;

    const float* x       = (const float*)d_in[0];
    const float* ctx     = (const float*)d_in[1];
    const float* sa_ng   = (const float*)d_in[2];
    const float* sa_nb   = (const float*)d_in[3];
    const float* sa_ncg  = (const float*)d_in[4];
    const float* sa_ncb  = (const float*)d_in[5];
    const float* sa_wq   = (const float*)d_in[6];
    const float* sa_wkv  = (const float*)d_in[7];
    const float* sa_wo   = (const float*)d_in[8];
    const float* sa_bo   = (const float*)d_in[9];
    const float* sa_rel  = (const float*)d_in[10];
    const float* ca_ng   = (const float*)d_in[11];
    const float* ca_nb   = (const float*)d_in[12];
    const float* ca_ncg  = (const float*)d_in[13];
    const float* ca_ncb  = (const float*)d_in[14];
    const float* ca_wq   = (const float*)d_in[15];
    const float* ca_wkv  = (const float*)d_in[16];
    const float* ca_wo   = (const float*)d_in[17];
    const float* ca_bo   = (const float*)d_in[18];
    const float* ca_rel  = (const float*)d_in[19];
    float* out = (float*)d_out;

    float *xn, *cn, *q, *kv, *ao, *x1, *tbl;
    cudaGetSymbolAddress((void**)&xn,  g_xn);
    cudaGetSymbolAddress((void**)&cn,  g_cn);
    cudaGetSymbolAddress((void**)&q,   g_q);
    cudaGetSymbolAddress((void**)&kv,  g_kv);
    cudaGetSymbolAddress((void**)&ao,  g_ao);
    cudaGetSymbolAddress((void**)&x1,  g_x1);
    cudaGetSymbolAddress((void**)&tbl, g_bias);

    // ---------------- self-attention ----------------
    bias_table_kernel<<<256, 256>>>(sa_rel, tbl);
    ln_kernel<<<ROWS_X, 256>>>(x, sa_ng,  sa_nb,  xn);
    ln_kernel<<<ROWS_X, 256>>>(x, sa_ncg, sa_ncb, cn);
    gemm_tc<<<dim3(MID / 128,     ROWS_X / 128), 256>>>(xn, sa_wq,  q,  ROWS_X, MID,     F, nullptr, nullptr);
    gemm_tc<<<dim3(2 * MID / 128, ROWS_X / 128), 256>>>(cn, sa_wkv, kv, ROWS_X, 2 * MID, F, nullptr, nullptr);
    attn_tc<<<dim3(NQ / 64, NHEAD, B), 128>>>(q, kv, ao, tbl, NQ, NQ, 0);
    gemm_tc<<<dim3(F / 128, ROWS_X / 128), 256>>>(ao, sa_wo, x1, ROWS_X, F, MID, sa_bo, x);

    // ---------------- cross-attention ----------------
    bias_table_kernel<<<256, 256>>>(ca_rel, tbl);
    ln_kernel<<<ROWS_X, 256>>>(x1,  ca_ng,  ca_nb,  xn);
    ln_kernel<<<ROWS_C, 256>>>(ctx, ca_ncg, ca_ncb, cn);
    gemm_tc<<<dim3(MID / 128,     ROWS_X / 128), 256>>>(xn, ca_wq,  q,  ROWS_X, MID,     F, nullptr, nullptr);
    gemm_tc<<<dim3(2 * MID / 128, ROWS_C / 128), 256>>>(cn, ca_wkv, kv, ROWS_C, 2 * MID, F, nullptr, nullptr);
    attn_tc<<<dim3(NQ / 64, NHEAD, B), 128>>>(q, kv, ao, tbl, NQ, NCTX, NCTX - NQ);
    gemm_tc<<<dim3(F / 128, ROWS_X / 128), 256>>>(ao, ca_wo, out, ROWS_X, F, MID, ca_bo, x1);
}

// round 3
// speedup vs baseline: 13.9219x; 2.9365x over previous
#include <cuda_runtime.h>
#include <cuda_bf16.h>
#include <math.h>
#include <math_constants.h>
#include <stdint.h>

// ---------------------------------------------------------------------------
// Problem constants
// ---------------------------------------------------------------------------
#define B        2
#define NQ       2048
#define NCTX     512
#define F        1024
#define MID      1024
#define NHEAD    16
#define HDIM     64
#define ROWS_X   (B * NQ)      // 4096
#define ROWS_C   (B * NCTX)    // 1024

// ---------------------------------------------------------------------------
// Scratch (device globals)
// ---------------------------------------------------------------------------
__device__ __nv_bfloat16 g_xn [ROWS_X * F];
__device__ __nv_bfloat16 g_cn [ROWS_X * F];
__device__ __nv_bfloat16 g_q  [ROWS_X * MID];
__device__ __nv_bfloat16 g_kv [ROWS_X * 2 * MID];
__device__ __nv_bfloat16 g_ao [ROWS_X * MID];
__device__ float         g_x1 [ROWS_X * F];
__device__ float         g_tbl[NHEAD * 4096];
__device__ __nv_bfloat16 g_wtq [MID * F];        // Wt[N][K]
__device__ __nv_bfloat16 g_wtkv[2 * MID * F];
__device__ __nv_bfloat16 g_wto [F * MID];

// ---------------------------------------------------------------------------
// PTX helpers
// ---------------------------------------------------------------------------
__device__ __forceinline__ uint32_t su32(const void* p) {
    return (uint32_t)__cvta_generic_to_shared(p);
}
__device__ __forceinline__ void cp16(uint32_t dst, const void* src) {
    asm volatile("cp.async.cg.shared.global [%0], [%1], 16;" :: "r"(dst), "l"(src));
}
__device__ __forceinline__ void cp_commit() {
    asm volatile("cp.async.commit_group;");
}
template<int N> __device__ __forceinline__ void cp_wait() {
    asm volatile("cp.async.wait_group %0;" :: "n"(N));
}
__device__ __forceinline__ void ldm_x4(uint32_t r[4], uint32_t addr) {
    asm volatile("ldmatrix.sync.aligned.m8n8.x4.shared.b16 {%0,%1,%2,%3}, [%4];"
                 : "=r"(r[0]), "=r"(r[1]), "=r"(r[2]), "=r"(r[3]) : "r"(addr));
}
__device__ __forceinline__ void ldm_x4_t(uint32_t r[4], uint32_t addr) {
    asm volatile("ldmatrix.sync.aligned.m8n8.x4.trans.shared.b16 {%0,%1,%2,%3}, [%4];"
                 : "=r"(r[0]), "=r"(r[1]), "=r"(r[2]), "=r"(r[3]) : "r"(addr));
}
__device__ __forceinline__ void mma_bf16(float c[4], const uint32_t a[4], const uint32_t b[2]) {
    asm volatile(
        "mma.sync.aligned.m16n8k16.row.col.f32.bf16.bf16.f32 "
        "{%0,%1,%2,%3}, {%4,%5,%6,%7}, {%8,%9}, {%0,%1,%2,%3};\n"
        : "+f"(c[0]), "+f"(c[1]), "+f"(c[2]), "+f"(c[3])
        : "r"(a[0]), "r"(a[1]), "r"(a[2]), "r"(a[3]), "r"(b[0]), "r"(b[1]));
}
__device__ __forceinline__ uint32_t packbf(float lo, float hi) {
    __nv_bfloat162 t = __floats2bfloat162_rn(lo, hi);
    return *reinterpret_cast<uint32_t*>(&t);
}

// ---------------------------------------------------------------------------
// LayerNorm (fp32 in -> bf16 out): one block (256 thr) per row of 1024
// ---------------------------------------------------------------------------
__global__ __launch_bounds__(256) void ln_kernel(
    const float* __restrict__ x, const float* __restrict__ g,
    const float* __restrict__ bta, __nv_bfloat16* __restrict__ out)
{
    __shared__ float red[8];
    const int row = blockIdx.x;
    const int tid = threadIdx.x;

    float4 v = ((const float4*)(x + (size_t)row * F))[tid];

    float s = v.x + v.y + v.z + v.w;
    #pragma unroll
    for (int o = 16; o > 0; o >>= 1) s += __shfl_xor_sync(0xffffffffu, s, o);
    if ((tid & 31) == 0) red[tid >> 5] = s;
    __syncthreads();
    float tot = 0.f;
    #pragma unroll
    for (int i = 0; i < 8; i++) tot += red[i];
    const float mean = tot * (1.0f / F);

    float dx = v.x - mean, dy = v.y - mean, dz = v.z - mean, dw = v.w - mean;
    float sq = dx * dx + dy * dy + dz * dz + dw * dw;
    #pragma unroll
    for (int o = 16; o > 0; o >>= 1) sq += __shfl_xor_sync(0xffffffffu, sq, o);
    __syncthreads();
    if ((tid & 31) == 0) red[tid >> 5] = sq;
    __syncthreads();
    float tsq = 0.f;
    #pragma unroll
    for (int i = 0; i < 8; i++) tsq += red[i];
    const float rs = rsqrtf(tsq * (1.0f / F) + 1e-5f);

    const float4 gv = ((const float4*)g)[tid];
    const float4 bv = ((const float4*)bta)[tid];
    __nv_bfloat162 p0 = __floats2bfloat162_rn(dx * rs * gv.x + bv.x, dy * rs * gv.y + bv.y);
    __nv_bfloat162 p1 = __floats2bfloat162_rn(dz * rs * gv.z + bv.z, dw * rs * gv.w + bv.w);
    uint2 u = make_uint2(*(uint32_t*)&p0, *(uint32_t*)&p1);
    *(uint2*)(out + (size_t)row * F + tid * 4) = u;
}

// ---------------------------------------------------------------------------
// Rel-pos bias table: tbl[h*4096 + rel + 2048] = emb[bucket(rel)*NHEAD + h]
// ---------------------------------------------------------------------------
__global__ __launch_bounds__(256) void bias_table_kernel(
    const float* __restrict__ emb, float* __restrict__ tbl)
{
    const int idx = blockIdx.x * 256 + threadIdx.x;
    const int h = idx >> 12;
    const int p = idx & 4095;
    const int rel = p - 2048;
    const int retv = (rel >= 0) ? 16 : 0;
    const int na = (rel < 0) ? -rel : rel;
    int bucket;
    if (na < 8) {
        bucket = retv + na;
    } else {
        float t = logf((float)na * 0.125f) / 2.7725887f;   // log(16)
        int vl = 8 + (int)(t * 8.0f);
        bucket = retv + min(vl, 15);
    }
    tbl[h * 4096 + p] = emb[bucket * NHEAD + h];
}

// ---------------------------------------------------------------------------
// Weight convert+transpose: W[K][N] fp32 -> Wt[N][K] bf16.  32x32 tiles.
// ---------------------------------------------------------------------------
__global__ __launch_bounds__(256) void wtrans_kernel(
    const float* __restrict__ W, __nv_bfloat16* __restrict__ Wt, int K, int N)
{
    __shared__ float t[32][33];
    const int n0 = blockIdx.x * 32, k0 = blockIdx.y * 32;
    const int tx = threadIdx.x, ty = threadIdx.y;   // 32 x 8
    #pragma unroll
    for (int i = 0; i < 4; i++)
        t[ty + 8 * i][tx] = W[(size_t)(k0 + ty + 8 * i) * N + n0 + tx];
    __syncthreads();
    #pragma unroll
    for (int i = 0; i < 4; i++)
        Wt[(size_t)(n0 + ty + 8 * i) * K + k0 + tx] = __float2bfloat16(t[tx][ty + 8 * i]);
}

// ---------------------------------------------------------------------------
// bf16 GEMM: C[M,N] = A[M,K] @ Bt[N,K]^T (+bias) (+res)
// 128x128 tile, Ktile 32, 8 warps (2x4), warp tile 64x32, double-buffered
// cp.async, ldmatrix fragments. Row stride pad: 40 bf16 (5 x 16B -> conflict-
// free ldmatrix, since 5r mod 8 is a permutation).
// ---------------------------------------------------------------------------
template<bool OBF>
__global__ __launch_bounds__(256) void gemm_bf16(
    const __nv_bfloat16* __restrict__ A, const __nv_bfloat16* __restrict__ Bt,
    void* __restrict__ Cv, int M, int N, int K,
    const float* __restrict__ bias, const float* __restrict__ res)
{
    __shared__ __nv_bfloat16 As[2][128 * 40];
    __shared__ __nv_bfloat16 Bs[2][128 * 40];

    const int tid = threadIdx.x;
    const int warp = tid >> 5, lane = tid & 31;
    const int q = lane >> 2, cq = lane & 3;
    const int wm = (warp >> 2) * 64, wn = (warp & 3) * 32;
    const int bm = blockIdx.y * 128, bn = blockIdx.x * 128;

    float acc[4][4][4];
    #pragma unroll
    for (int mt = 0; mt < 4; mt++)
        #pragma unroll
        for (int nt = 0; nt < 4; nt++)
            #pragma unroll
            for (int e = 0; e < 4; e++) acc[mt][nt][e] = 0.f;

    const int lr = tid >> 2;             // load row 0..63 (+64)
    const int lc = (tid & 3) * 8;        // 16B chunk

    auto load_tile = [&](int kt, int bi) {
        const __nv_bfloat16* Ag = A + (size_t)bm * K + kt * 32 + lc;
        const __nv_bfloat16* Bg = Bt + (size_t)bn * K + kt * 32 + lc;
        cp16(su32(&As[bi][lr * 40 + lc]),        Ag + (size_t)lr * K);
        cp16(su32(&As[bi][(lr + 64) * 40 + lc]), Ag + (size_t)(lr + 64) * K);
        cp16(su32(&Bs[bi][lr * 40 + lc]),        Bg + (size_t)lr * K);
        cp16(su32(&Bs[bi][(lr + 64) * 40 + lc]), Bg + (size_t)(lr + 64) * K);
    };

    load_tile(0, 0); cp_commit();
    const int KT = K / 32;

    for (int kt = 0; kt < KT; kt++) {
        if (kt + 1 < KT) { load_tile(kt + 1, (kt + 1) & 1); cp_commit(); cp_wait<1>(); }
        else             { cp_wait<0>(); }
        __syncthreads();

        const __nv_bfloat16* as = As[kt & 1];
        const __nv_bfloat16* bs = Bs[kt & 1];
        #pragma unroll
        for (int ks = 0; ks < 2; ks++) {
            uint32_t af[4][4], bfr[2][4];
            #pragma unroll
            for (int mt = 0; mt < 4; mt++) {
                const int row = wm + mt * 16 + ((lane >> 3) & 1) * 8 + (lane & 7);
                const int col = ks * 16 + (lane >> 4) * 8;
                ldm_x4(af[mt], su32(as + row * 40 + col));
            }
            #pragma unroll
            for (int pn = 0; pn < 2; pn++) {
                const int row = wn + pn * 16 + (lane >> 4) * 8 + (lane & 7);
                const int col = ks * 16 + ((lane >> 3) & 1) * 8;
                ldm_x4(bfr[pn], su32(bs + row * 40 + col));
            }
            #pragma unroll
            for (int mt = 0; mt < 4; mt++)
                #pragma unroll
                for (int nt = 0; nt < 4; nt++)
                    mma_bf16(acc[mt][nt], af[mt], &bfr[nt >> 1][(nt & 1) * 2]);
        }
        __syncthreads();
    }

    // epilogue
    #pragma unroll
    for (int mt = 0; mt < 4; mt++) {
        #pragma unroll
        for (int nt = 0; nt < 4; nt++) {
            const int c0 = bn + wn + nt * 8 + 2 * cq;
            #pragma unroll
            for (int half = 0; half < 2; half++) {
                const int row = bm + wm + mt * 16 + q + half * 8;
                float v0 = acc[mt][nt][half * 2 + 0];
                float v1 = acc[mt][nt][half * 2 + 1];
                const size_t base = (size_t)row * N + c0;
                if (OBF) {
                    __nv_bfloat16* C = (__nv_bfloat16*)Cv;
                    *(uint32_t*)(C + base) = packbf(v0, v1);
                } else {
                    float* C = (float*)Cv;
                    if (bias) { v0 += bias[c0]; v1 += bias[c0 + 1]; }
                    if (res)  { v0 += res[base]; v1 += res[base + 1]; }
                    *(float2*)(C + base) = make_float2(v0, v1);
                }
            }
        }
    }
}

// ---------------------------------------------------------------------------
// Flash attention, bf16 MMA. Block = 128 thr (4 warps) = one (b,h,64-q tile).
// K tile [j][d], V tile [j][d] (trans ldmatrix for PV B-frags), rows padded
// to 72 bf16 (9 x 16B -> conflict-free). P stays in registers (c-frag layout
// of S is exactly the a-frag layout of PV after bf16x2 pack).
// ---------------------------------------------------------------------------
__global__ __launch_bounds__(128) void attn_bf16(
    const __nv_bfloat16* __restrict__ qb, const __nv_bfloat16* __restrict__ kvb,
    __nv_bfloat16* __restrict__ ob, const float* __restrict__ tbl,
    int n, int m, int mnoff)
{
    __shared__ __nv_bfloat16 Ks[2][64 * 72];
    __shared__ __nv_bfloat16 Vs[2][64 * 72];
    __shared__ float sb[128];

    const int tid = threadIdx.x;
    const int warp = tid >> 5, lane = tid & 31;
    const int q = lane >> 2, cq = lane & 3;
    const int b = blockIdx.z, h = blockIdx.y;
    const int q0 = blockIdx.x * 64;
    const int r0l = warp * 16 + q;
    const int r1l = r0l + 8;

    // Q fragments (bf16x2 pairs straight from global)
    uint32_t qf[4][4];
    {
        const __nv_bfloat16* qr0 = qb + (size_t)(b * n + q0 + r0l) * MID + h * HDIM;
        const __nv_bfloat16* qr1 = qr0 + 8 * (size_t)MID;
        #pragma unroll
        for (int ks = 0; ks < 4; ks++) {
            qf[ks][0] = *(const uint32_t*)(qr0 + ks * 16 + cq * 2);
            qf[ks][1] = *(const uint32_t*)(qr1 + ks * 16 + cq * 2);
            qf[ks][2] = *(const uint32_t*)(qr0 + ks * 16 + cq * 2 + 8);
            qf[ks][3] = *(const uint32_t*)(qr1 + ks * 16 + cq * 2 + 8);
        }
    }

    float o[8][4];
    #pragma unroll
    for (int dt = 0; dt < 8; dt++)
        #pragma unroll
        for (int e = 0; e < 4; e++) o[dt][e] = 0.f;
    float mrun0 = -CUDART_INF_F, mrun1 = -CUDART_INF_F;
    float lrun0 = 0.f, lrun1 = 0.f;

    const __nv_bfloat16* kvbase = kvb + (size_t)(b * m) * (2 * MID) + h * HDIM;
    const float* tblh = tbl + h * 4096;
    const int lr0 = tid >> 3;           // load row base 0..15
    const int lc8 = (tid & 7) * 8;      // 16B chunk in 128B row

    auto load_kv = [&](int c, int bi) {
        const __nv_bfloat16* kg = kvbase + (size_t)(c * 64) * (2 * MID);
        #pragma unroll
        for (int i = 0; i < 4; i++) {
            const int r = lr0 + i * 16;
            cp16(su32(&Ks[bi][r * 72 + lc8]), kg + (size_t)r * (2 * MID) + lc8);
            cp16(su32(&Vs[bi][r * 72 + lc8]), kg + MID + (size_t)r * (2 * MID) + lc8);
        }
    };

    const int C = m / 64;
    load_kv(0, 0); cp_commit();

    for (int c = 0; c < C; c++) {
        if (c + 1 < C) { load_kv(c + 1, (c + 1) & 1); cp_commit(); cp_wait<1>(); }
        else           { cp_wait<0>(); }
        __syncthreads();

        // bias slice for this chunk: sb[t] = bias at (j - r) = t - 63
        const int base = 2048 + c * 64 - q0 - mnoff;
        if (tid < 127) sb[tid] = tblh[base + tid - 63];
        __syncthreads();

        const __nv_bfloat16* ks_b = Ks[c & 1];
        const __nv_bfloat16* vs_b = Vs[c & 1];

        // ---- S = Q @ K^T ----
        float s[8][4];
        #pragma unroll
        for (int nt = 0; nt < 8; nt++)
            #pragma unroll
            for (int e = 0; e < 4; e++) s[nt][e] = 0.f;

        #pragma unroll
        for (int ks = 0; ks < 4; ks++) {
            uint32_t bfr[4][4];
            #pragma unroll
            for (int pn = 0; pn < 4; pn++) {
                const int row = pn * 16 + (lane >> 4) * 8 + (lane & 7);
                const int col = ks * 16 + ((lane >> 3) & 1) * 8;
                ldm_x4(bfr[pn], su32(ks_b + row * 72 + col));
            }
            #pragma unroll
            for (int nt = 0; nt < 8; nt++)
                mma_bf16(s[nt], qf[ks], &bfr[nt >> 1][(nt & 1) * 2]);
        }

        // ---- bias + scale + row max ----
        float cmax0 = -CUDART_INF_F, cmax1 = -CUDART_INF_F;
        #pragma unroll
        for (int nt = 0; nt < 8; nt++) {
            #pragma unroll
            for (int e = 0; e < 2; e++) {
                const int jl = nt * 8 + 2 * cq + e;
                s[nt][e]     = (s[nt][e]     + sb[jl - r0l + 63]) * 0.125f;
                s[nt][2 + e] = (s[nt][2 + e] + sb[jl - r1l + 63]) * 0.125f;
                cmax0 = fmaxf(cmax0, s[nt][e]);
                cmax1 = fmaxf(cmax1, s[nt][2 + e]);
            }
        }
        cmax0 = fmaxf(cmax0, __shfl_xor_sync(0xffffffffu, cmax0, 1));
        cmax0 = fmaxf(cmax0, __shfl_xor_sync(0xffffffffu, cmax0, 2));
        cmax1 = fmaxf(cmax1, __shfl_xor_sync(0xffffffffu, cmax1, 1));
        cmax1 = fmaxf(cmax1, __shfl_xor_sync(0xffffffffu, cmax1, 2));

        const float mn0 = fmaxf(mrun0, cmax0);
        const float mn1 = fmaxf(mrun1, cmax1);
        const float al0 = __expf(mrun0 - mn0);
        const float al1 = __expf(mrun1 - mn1);

        // ---- exp + partial sums (P kept in s[][] registers) ----
        float ps0 = 0.f, ps1 = 0.f;
        #pragma unroll
        for (int nt = 0; nt < 8; nt++) {
            #pragma unroll
            for (int e = 0; e < 2; e++) {
                s[nt][e]     = __expf(s[nt][e]     - mn0);
                s[nt][2 + e] = __expf(s[nt][2 + e] - mn1);
                ps0 += s[nt][e];
                ps1 += s[nt][2 + e];
            }
        }
        ps0 += __shfl_xor_sync(0xffffffffu, ps0, 1);
        ps0 += __shfl_xor_sync(0xffffffffu, ps0, 2);
        ps1 += __shfl_xor_sync(0xffffffffu, ps1, 1);
        ps1 += __shfl_xor_sync(0xffffffffu, ps1, 2);

        lrun0 = lrun0 * al0 + ps0;
        lrun1 = lrun1 * al1 + ps1;
        #pragma unroll
        for (int dt = 0; dt < 8; dt++) {
            o[dt][0] *= al0; o[dt][1] *= al0;
            o[dt][2] *= al1; o[dt][3] *= al1;
        }
        mrun0 = mn0; mrun1 = mn1;

        // ---- O += P @ V  (A-frags packed from S c-frags; B via ldmatrix.trans)
        #pragma unroll
        for (int kt = 0; kt < 4; kt++) {
            uint32_t ap[4];
            ap[0] = packbf(s[2 * kt][0],     s[2 * kt][1]);
            ap[1] = packbf(s[2 * kt][2],     s[2 * kt][3]);
            ap[2] = packbf(s[2 * kt + 1][0], s[2 * kt + 1][1]);
            ap[3] = packbf(s[2 * kt + 1][2], s[2 * kt + 1][3]);
            #pragma unroll
            for (int dp = 0; dp < 4; dp++) {
                uint32_t bv[4];
                const int row = kt * 16 + ((lane >> 3) & 1) * 8 + (lane & 7);
                const int col = dp * 16 + (lane >> 4) * 8;
                ldm_x4_t(bv, su32(vs_b + row * 72 + col));
                mma_bf16(o[2 * dp],     ap, &bv[0]);
                mma_bf16(o[2 * dp + 1], ap, &bv[2]);
            }
        }
        __syncthreads();   // all reads of this chunk's buffers done
    }

    // ---- normalize + store (bf16) ----
    const float inv0 = 1.0f / lrun0;
    const float inv1 = 1.0f / lrun1;
    __nv_bfloat16* or0 = ob + (size_t)(b * n + q0 + r0l) * MID + h * HDIM;
    __nv_bfloat16* or1 = ob + (size_t)(b * n + q0 + r1l) * MID + h * HDIM;
    #pragma unroll
    for (int dt = 0; dt < 8; dt++) {
        const int cc = dt * 8 + 2 * cq;
        *(uint32_t*)(or0 + cc) = packbf(o[dt][0] * inv0, o[dt][1] * inv0);
        *(uint32_t*)(or1 + cc) = packbf(o[dt][2] * inv1, o[dt][3] * inv1);
    }
}

// ---------------------------------------------------------------------------
// Launch
// ---------------------------------------------------------------------------
extern "C" void kernel_launch(void* const* d_in, const int* in_sizes, int n_in,
                              void* d_out, int out_size)
{
    (void)in_sizes; (void)n_in; (void)out_size;

    const float* x       = (const float*)d_in[0];
    const float* ctx     = (const float*)d_in[1];
    const float* sa_ng   = (const float*)d_in[2];
    const float* sa_nb   = (const float*)d_in[3];
    const float* sa_ncg  = (const float*)d_in[4];
    const float* sa_ncb  = (const float*)d_in[5];
    const float* sa_wq   = (const float*)d_in[6];
    const float* sa_wkv  = (const float*)d_in[7];
    const float* sa_wo   = (const float*)d_in[8];
    const float* sa_bo   = (const float*)d_in[9];
    const float* sa_rel  = (const float*)d_in[10];
    const float* ca_ng   = (const float*)d_in[11];
    const float* ca_nb   = (const float*)d_in[12];
    const float* ca_ncg  = (const float*)d_in[13];
    const float* ca_ncb  = (const float*)d_in[14];
    const float* ca_wq   = (const float*)d_in[15];
    const float* ca_wkv  = (const float*)d_in[16];
    const float* ca_wo   = (const float*)d_in[17];
    const float* ca_bo   = (const float*)d_in[18];
    const float* ca_rel  = (const float*)d_in[19];
    float* out = (float*)d_out;

    __nv_bfloat16 *xn, *cn, *q, *kv, *ao, *wtq, *wtkv, *wto;
    float *x1, *tbl;
    cudaGetSymbolAddress((void**)&xn,   g_xn);
    cudaGetSymbolAddress((void**)&cn,   g_cn);
    cudaGetSymbolAddress((void**)&q,    g_q);
    cudaGetSymbolAddress((void**)&kv,   g_kv);
    cudaGetSymbolAddress((void**)&ao,   g_ao);
    cudaGetSymbolAddress((void**)&x1,   g_x1);
    cudaGetSymbolAddress((void**)&tbl,  g_tbl);
    cudaGetSymbolAddress((void**)&wtq,  g_wtq);
    cudaGetSymbolAddress((void**)&wtkv, g_wtkv);
    cudaGetSymbolAddress((void**)&wto,  g_wto);

    const dim3 tb(32, 8);

    // ---------------- self-attention ----------------
    bias_table_kernel<<<256, 256>>>(sa_rel, tbl);
    wtrans_kernel<<<dim3(MID / 32,     F / 32),   tb>>>(sa_wq,  wtq,  F,   MID);
    wtrans_kernel<<<dim3(2 * MID / 32, F / 32),   tb>>>(sa_wkv, wtkv, F,   2 * MID);
    wtrans_kernel<<<dim3(F / 32,       MID / 32), tb>>>(sa_wo,  wto,  MID, F);
    ln_kernel<<<ROWS_X, 256>>>(x, sa_ng,  sa_nb,  xn);
    ln_kernel<<<ROWS_X, 256>>>(x, sa_ncg, sa_ncb, cn);
    gemm_bf16<true ><<<dim3(MID / 128,     ROWS_X / 128), 256>>>(xn, wtq,  q,  ROWS_X, MID,     F, nullptr, nullptr);
    gemm_bf16<true ><<<dim3(2 * MID / 128, ROWS_X / 128), 256>>>(cn, wtkv, kv, ROWS_X, 2 * MID, F, nullptr, nullptr);
    attn_bf16<<<dim3(NQ / 64, NHEAD, B), 128>>>(q, kv, ao, tbl, NQ, NQ, 0);
    gemm_bf16<false><<<dim3(F / 128, ROWS_X / 128), 256>>>(ao, wto, x1, ROWS_X, F, MID, sa_bo, x);

    // ---------------- cross-attention ----------------
    bias_table_kernel<<<256, 256>>>(ca_rel, tbl);
    wtrans_kernel<<<dim3(MID / 32,     F / 32),   tb>>>(ca_wq,  wtq,  F,   MID);
    wtrans_kernel<<<dim3(2 * MID / 32, F / 32),   tb>>>(ca_wkv, wtkv, F,   2 * MID);
    wtrans_kernel<<<dim3(F / 32,       MID / 32), tb>>>(ca_wo,  wto,  MID, F);
    ln_kernel<<<ROWS_X, 256>>>(x1,  ca_ng,  ca_nb,  xn);
    ln_kernel<<<ROWS_C, 256>>>(ctx, ca_ncg, ca_ncb, cn);
    gemm_bf16<true ><<<dim3(MID / 128,     ROWS_X / 128), 256>>>(xn, wtq,  q,  ROWS_X, MID,     F, nullptr, nullptr);
    gemm_bf16<true ><<<dim3(2 * MID / 128, ROWS_C / 128), 256>>>(cn, wtkv, kv, ROWS_C, 2 * MID, F, nullptr, nullptr);
    attn_bf16<<<dim3(NQ / 64, NHEAD, B), 128>>>(q, kv, ao, tbl, NQ, NCTX, NCTX - NQ);
    gemm_bf16<false><<<dim3(F / 128, ROWS_X / 128), 256>>>(ao, wto, out, ROWS_X, F, MID, ca_bo, x1);
}